// round 13
// baseline (speedup 1.0000x reference)
#include <cuda_runtime.h>

#define NN 4096
#define FIN 128
#define FOUT 64
#define HH 4
#define CC 256            // HH*FOUT
#define NEG_INF (-1e9f)
#define RC2 32            // row chunks in stats pass (128 rows each)
#define NSTRIP 16         // column strips in stats pass
#define NJC 4             // j-chunks in main pass
#define JC 1024           // columns per j-chunk
#define IT 32             // i rows per block in main pass
#define MST 40            // mask smem i-stride: A-frag LDS.64 conflict-free
#define MBUFW (IT * MST)  // 1280 words
#define PJB 72            // B smem jp-stride: B-frag lanes hit 32 distinct banks
#define PHB (16 * PJB)    // per-head: 16 j-pairs = 1152 words
#define PBW (HH * PHB)    // 4608 words
#define K3BUF (MBUFW + PBW)       // 5888 words per stage
#define K3_DYN (2 * K3BUF * 4)    // 47104 bytes dynamic smem

// ---------------- scratch (static device globals; fully rewritten each call) ----------
__device__ float g_proj[HH * NN * FOUT];        // [h][n][f] f32
__device__ unsigned g_projh[HH * (NN / 2) * FOUT]; // proj*cinv, half2 (j-even lo, j-odd hi)
__device__ float g_ssrc[HH * NN];
__device__ float g_stgt[HH * NN];
__device__ float g_skip[NN * CC];
__device__ float g_csp[RC2 * HH * NN];          // col exp-sum partials (shifted by -8)
__device__ float g_mask[(size_t)NN * NN];       // 64MB: mask - 8
__device__ float g_agg[NJC * NN * CC];          // partial out per j-chunk

// ---------------- helpers ----------------
__device__ __forceinline__ unsigned long long pk2(float x, float y) {
    unsigned long long r;
    asm("mov.b64 %0, {%1,%2};" : "=l"(r) : "f"(x), "f"(y));
    return r;
}
__device__ __forceinline__ void upk2(unsigned long long v, float& x, float& y) {
    asm("mov.b64 {%0,%1}, %2;" : "=f"(x), "=f"(y) : "l"(v));
}
__device__ __forceinline__ unsigned long long fma2(unsigned long long a,
                                                   unsigned long long b,
                                                   unsigned long long c) {
    unsigned long long d;
    asm("fma.rn.f32x2 %0, %1, %2, %3;" : "=l"(d) : "l"(a), "l"(b), "l"(c));
    return d;
}
// Pack two f32 -> f16x2 (same helper for A and B so hw convention cancels in k-dot)
__device__ __forceinline__ unsigned pkh2(float lo, float hi) {
    unsigned r;
    asm("cvt.rn.f16x2.f32 %0, %2, %1;" : "=r"(r) : "f"(lo), "f"(hi));
    return r;
}
__device__ __forceinline__ void mma_f16(float* d, const unsigned* a,
                                        unsigned b0, unsigned b1) {
    asm volatile(
        "mma.sync.aligned.m16n8k16.row.col.f32.f16.f16.f32 "
        "{%0,%1,%2,%3},{%4,%5,%6,%7},{%8,%9},{%0,%1,%2,%3};"
        : "+f"(d[0]), "+f"(d[1]), "+f"(d[2]), "+f"(d[3])
        : "r"(a[0]), "r"(a[1]), "r"(a[2]), "r"(a[3]), "r"(b0), "r"(b1));
}
__device__ __forceinline__ void cpa16(unsigned dst, const void* src) {
    asm volatile("cp.async.cg.shared.global [%0], [%1], 16;" :: "r"(dst), "l"(src));
}
__device__ __forceinline__ void cpa_commit() {
    asm volatile("cp.async.commit_group;");
}
template <int N> __device__ __forceinline__ void cpa_wait() {
    asm volatile("cp.async.wait_group %0;" :: "n"(N));
}

// ---------------- K1: proj + skip GEMMs (f32x2 packed) + scalar scores --------------
__global__ void k1_proj_skip_scores(const float* __restrict__ nodes,
                                    const float* __restrict__ pp,
                                    const float* __restrict__ sw,
                                    const float* __restrict__ s_src,
                                    const float* __restrict__ s_tgt) {
    __shared__ float nsT[FIN][34];   // transposed, padded: row pairs 8B-aligned
    int tid = threadIdx.x;
    int ib = blockIdx.x * 32;
    for (int x = tid; x < 32 * FIN; x += 256) {
        int row = x >> 7, col = x & 127;
        nsT[col][row] = nodes[ib * FIN + x];
    }
    __syncthreads();
    int c = tid, h = c >> 6, f = c & 63;
    unsigned long long aP2[16], aS2[16];
#pragma unroll
    for (int r = 0; r < 16; r++) { aP2[r] = 0ull; aS2[r] = 0ull; }
#pragma unroll 2
    for (int k = 0; k < FIN; k++) {
        float w1 = pp[h * (FIN * FOUT) + k * FOUT + f];
        float w2 = sw[c * FIN + k];
        unsigned long long W1 = pk2(w1, w1), W2 = pk2(w2, w2);
        const unsigned long long* nv = (const unsigned long long*)&nsT[k][0];
#pragma unroll
        for (int rp = 0; rp < 16; rp++) {
            unsigned long long nn = nv[rp];
            aP2[rp] = fma2(nn, W1, aP2[rp]);
            aS2[rp] = fma2(nn, W2, aS2[rp]);
        }
    }
#pragma unroll
    for (int rp = 0; rp < 16; rp++) {
        float lo, hi;
        upk2(aP2[rp], lo, hi);
        g_proj[(h * NN + ib + 2 * rp) * FOUT + f] = lo;
        g_proj[(h * NN + ib + 2 * rp + 1) * FOUT + f] = hi;
        upk2(aS2[rp], lo, hi);
        g_skip[(ib + 2 * rp) * CC + c] = lo;
        g_skip[(ib + 2 * rp + 1) * CC + c] = hi;
    }
    __syncthreads();   // block-scope visibility of g_proj stores
    {
        int r = tid >> 3;
        int h2 = (tid >> 1) & 3;
        int which = tid & 1;
        const float* pr = &g_proj[(h2 * NN + ib + r) * FOUT];
        const float* wv = (which ? s_tgt : s_src) + h2 * FOUT;
        float a = 0.f;
#pragma unroll 8
        for (int ff = 0; ff < FOUT; ff++) a = fmaf(pr[ff], wv[ff], a);
        if (which) g_stgt[h2 * NN + ib + r] = a;
        else       g_ssrc[h2 * NN + ib + r] = a;
    }
}

// ---------------- K2: stats pass (writes mask-8; col exp-sums ONLY) ----------------
__global__ void k2_stats(const float* __restrict__ deg,
                         const float* __restrict__ bond,
                         const float* __restrict__ cutp) {
    __shared__ float ssS[HH][128];
    int tid = threadIdx.x;
    int s = blockIdx.x, rc = blockIdx.y;
    int j = s * 256 + tid;
    int i0 = rc * 128;
    float cut = *cutp;
    for (int x = tid; x < HH * 128; x += 256)
        ssS[x >> 7][x & 127] = g_ssrc[(x >> 7) * NN + i0 + (x & 127)];
    __syncthreads();
    float st[HH], sm[HH];
#pragma unroll
    for (int h = 0; h < HH; h++) {
        st[h] = g_stgt[h * NN + j];
        sm[h] = 0.f;
    }
    for (int li0 = 0; li0 < 128; li0 += 4) {
        float dv[4], bv[4];
#pragma unroll
        for (int k = 0; k < 4; k++) {
            size_t off = (size_t)(i0 + li0 + k) * NN + j;
            dv[k] = deg[off];
            bv[k] = bond[off];
        }
#pragma unroll
        for (int k = 0; k < 4; k++) {
            int li = li0 + k;
            int i = i0 + li;
            float wdm = dv[k] + bv[k];
            float mask = (wdm > 0.f) ? wdm : ((bv[k] > cut) ? (bv[k] + wdm) : NEG_INF);
            mask -= 8.0f;   // global shift: fp16 exp headroom (cancels in softmax)
            g_mask[(size_t)i * NN + j] = mask;
#pragma unroll
            for (int h = 0; h < HH; h++) {
                float t = ssS[h][li] + st[h];
                float x = fmaxf(t, 0.2f * t) + mask;
                sm[h] += __expf(x);
            }
        }
    }
#pragma unroll
    for (int h = 0; h < HH; h++)
        g_csp[(rc * HH + h) * NN + j] = sm[h];
}

// ---------------- K2bc: col partials -> projh (half2 j-pairs) ----------------
__global__ void k2bc_combine() {
    int t = blockIdx.x * 256 + threadIdx.x;   // 0..8191 = h*2048 + jp
    int h = t >> 11, jp = t & 2047;
    int j0 = 2 * jp, j1 = j0 + 1;
    float S0 = 0.f, S1 = 0.f;
#pragma unroll
    for (int rc = 0; rc < RC2; rc++) {
        S0 += g_csp[(rc * HH + h) * NN + j0];
        S1 += g_csp[(rc * HH + h) * NN + j1];
    }
    float ci0 = 1.0f / S0, ci1 = 1.0f / S1;
    const float4* p0 = (const float4*)&g_proj[((size_t)h * NN + j0) * FOUT];
    const float4* p1 = (const float4*)&g_proj[((size_t)h * NN + j1) * FOUT];
    uint4* dst = (uint4*)&g_projh[((size_t)h * 2048 + jp) * FOUT];
#pragma unroll
    for (int q = 0; q < FOUT / 4; q++) {
        float4 a = p0[q], b = p1[q];
        uint4 o;
        o.x = pkh2(a.x * ci0, b.x * ci1);
        o.y = pkh2(a.y * ci0, b.y * ci1);
        o.z = pkh2(a.z * ci0, b.z * ci1);
        o.w = pkh2(a.w * ci0, b.w * ci1);
        dst[q] = o;
    }
}

// ---------------- K3: fp16 m16n8k16 attn@projc, cp.async 2-buf, 3 blocks/SM --------
// grid (NJC, 128), block 256 = 8 warps. Warp w: head h=w&3, ihalf=w>>2 (16 rows).
__global__ __launch_bounds__(256, 3) void k3_main() {
    extern __shared__ float smdyn[];
    unsigned sbase = (unsigned)__cvta_generic_to_shared(smdyn);
    int tid = threadIdx.x;
    int jc = blockIdx.x;
    int ib = blockIdx.y * IT;

    int lane = tid & 31;
    int w = tid >> 5;
    int h = w & 3;
    int ihalf = w >> 2;
    int t4 = lane & 3, tg4 = lane >> 2;

    int r_ = ihalf * 16 + tg4;
    float ssv0 = g_ssrc[h * NN + ib + r_];
    float ssv1 = g_ssrc[h * NN + ib + r_ + 8];

    int mi = tid >> 3, mjq = (tid & 7) * 4;   // staging: 1 row x 4 cols per thread

    float acc[8][4];
#pragma unroll
    for (int nt = 0; nt < 8; nt++)
#pragma unroll
        for (int e = 0; e < 4; e++) acc[nt][e] = 0.f;

    auto stage = [&](int t, int buf) {
        int jb = jc * JC + t * 32;
        unsigned mb = sbase + (buf * K3BUF) * 4;
        unsigned pb = mb + MBUFW * 4;
        cpa16(mb + (mi * MST + mjq) * 4,
              &g_mask[(size_t)(ib + mi) * NN + jb + mjq]);
#pragma unroll
        for (int x = 0; x < 4; x++) {
            int c = tid + x * 256;               // 0..1023
            int hh = c >> 8, jp = (c >> 4) & 15, f4 = (c & 15) * 4;
            cpa16(pb + (hh * PHB + jp * PJB + f4) * 4,
                  &g_projh[((size_t)hh * 2048 + (jb >> 1) + jp) * FOUT + f4]);
        }
        cpa_commit();
    };

    stage(0, 0);

    for (int t0 = 0; t0 < JC / 32; t0++) {
        if (t0 + 1 < JC / 32) {
            stage(t0 + 1, (t0 + 1) & 1);
            cpa_wait<1>();
        } else {
            cpa_wait<0>();
        }
        __syncthreads();

        int jb = jc * JC + t0 * 32;
        const float* mb = smdyn + (t0 & 1) * K3BUF;
        const unsigned* pS = (const unsigned*)(mb + MBUFW);

#pragma unroll
        for (int kt = 0; kt < 2; kt++) {
            int cb = kt * 16 + 2 * t4;
            float2 stA = *(const float2*)&g_stgt[h * NN + jb + cb];
            float2 stB = *(const float2*)&g_stgt[h * NN + jb + cb + 8];
            float2 mA0 = *(const float2*)&mb[r_ * MST + cb];
            float2 mA1 = *(const float2*)&mb[(r_ + 8) * MST + cb];
            float2 mB0 = *(const float2*)&mb[r_ * MST + cb + 8];
            float2 mB1 = *(const float2*)&mb[(r_ + 8) * MST + cb + 8];
            float t00 = ssv0 + stA.x, t01 = ssv0 + stA.y;
            float t10 = ssv1 + stA.x, t11 = ssv1 + stA.y;
            float t02 = ssv0 + stB.x, t03 = ssv0 + stB.y;
            float t12 = ssv1 + stB.x, t13 = ssv1 + stB.y;
            float e00 = __expf(fmaxf(t00, 0.2f * t00) + mA0.x);
            float e01 = __expf(fmaxf(t01, 0.2f * t01) + mA0.y);
            float e10 = __expf(fmaxf(t10, 0.2f * t10) + mA1.x);
            float e11 = __expf(fmaxf(t11, 0.2f * t11) + mA1.y);
            float e02 = __expf(fmaxf(t02, 0.2f * t02) + mB0.x);
            float e03 = __expf(fmaxf(t03, 0.2f * t03) + mB0.y);
            float e12 = __expf(fmaxf(t12, 0.2f * t12) + mB1.x);
            float e13 = __expf(fmaxf(t13, 0.2f * t13) + mB1.y);
            unsigned a[4];
            a[0] = pkh2(e00, e01);   // row r_,   k-low pair
            a[1] = pkh2(e10, e11);   // row r_+8, k-low pair
            a[2] = pkh2(e02, e03);   // row r_,   k-high pair
            a[3] = pkh2(e12, e13);   // row r_+8, k-high pair
            const unsigned* pbp = &pS[h * PHB + (kt * 8 + t4) * PJB + tg4];
#pragma unroll
            for (int nt = 0; nt < 8; nt++) {
                unsigned b0 = pbp[nt * 8];
                unsigned b1 = pbp[nt * 8 + 4 * PJB];
                mma_f16(acc[nt], a, b0, b1);
            }
        }
        __syncthreads();
    }
    // ---- epilogue: fragment store to g_agg ----
#pragma unroll
    for (int nt = 0; nt < 8; nt++) {
        int i0 = ib + r_;
        int c0 = h * 64 + nt * 8 + 2 * t4;
        *(float2*)&g_agg[((size_t)jc * NN + i0) * CC + c0] =
            make_float2(acc[nt][0], acc[nt][1]);
        *(float2*)&g_agg[((size_t)jc * NN + i0 + 8) * CC + c0] =
            make_float2(acc[nt][2], acc[nt][3]);
    }
}

// ---------------- kRowLN: one block per row; full-row stats + LN write --------------
__global__ void kRowLN(float* __restrict__ out_ln) {
    __shared__ float sp[8], sq[8], sbc[2];
    int i = blockIdx.x;
    int tid = threadIdx.x;
    int lane = tid & 31, w = tid >> 5;
    const float4* src = (const float4*)&g_mask[(size_t)i * NN];
    float4 v[4];
    float s = 0.f, q = 0.f;
#pragma unroll
    for (int t = 0; t < 4; t++) {               // tid + 256t covers all 1024 float4
        v[t] = src[tid + 256 * t];
        s += v[t].x + v[t].y + v[t].z + v[t].w;
        q = fmaf(v[t].x, v[t].x, q);
        q = fmaf(v[t].y, v[t].y, q);
        q = fmaf(v[t].z, v[t].z, q);
        q = fmaf(v[t].w, v[t].w, q);
    }
#pragma unroll
    for (int off = 16; off > 0; off >>= 1) {
        s += __shfl_xor_sync(0xffffffffu, s, off);
        q += __shfl_xor_sync(0xffffffffu, q, off);
    }
    if (lane == 0) { sp[w] = s; sq[w] = q; }
    __syncthreads();
    if (tid == 0) {
        float S = 0.f, Q = 0.f;
#pragma unroll
        for (int x = 0; x < 8; x++) { S += sp[x]; Q += sq[x]; }
        float mu = S * (1.0f / NN);             // shifted mu' (shift cancels in m - mu)
        float var = Q * (1.0f / NN) - mu * mu;  // variance is shift-invariant
        sbc[0] = mu;
        sbc[1] = rsqrtf(var + 1e-5f);
    }
    __syncthreads();
    float mu = sbc[0], rs = sbc[1];
    float4* dst = (float4*)&out_ln[(size_t)i * NN];
#pragma unroll
    for (int t = 0; t < 4; t++) {
        float4 r;
        r.x = (v[t].x - mu) * rs; r.y = (v[t].y - mu) * rs;
        r.z = (v[t].z - mu) * rs; r.w = (v[t].w - mu) * rs;
        dst[tid + 256 * t] = r;
    }
}

// ---------------- K4: epilogue: sum partials + skip, ELU (float4) ----------------
__global__ void k4_epilogue(float* __restrict__ out0) {
    int t = blockIdx.x * 256 + threadIdx.x;
    const float4* sk = (const float4*)g_skip;
    float4 v = sk[t];
#pragma unroll
    for (int jc = 0; jc < NJC; jc++) {
        float4 a = ((const float4*)g_agg)[(size_t)jc * (NN * CC / 4) + t];
        v.x += a.x; v.y += a.y; v.z += a.z; v.w += a.w;
    }
    float4 r;
    r.x = (v.x > 0.f) ? v.x : expm1f(v.x);
    r.y = (v.y > 0.f) ? v.y : expm1f(v.y);
    r.z = (v.z > 0.f) ? v.z : expm1f(v.z);
    r.w = (v.w > 0.f) ? v.w : expm1f(v.w);
    ((float4*)out0)[t] = r;
}

// ---------------- launch ----------------
extern "C" void kernel_launch(void* const* d_in, const int* in_sizes, int n_in,
                              void* d_out, int out_size) {
    const float* nodes = (const float*)d_in[0];
    const float* deg   = (const float*)d_in[1];
    const float* bond  = (const float*)d_in[3];
    const float* pp    = (const float*)d_in[4];
    const float* ssw   = (const float*)d_in[5];
    const float* stw   = (const float*)d_in[6];
    const float* sw    = (const float*)d_in[7];
    const float* cutp  = (const float*)d_in[8];

    float* out0 = (float*)d_out;                  // [N, 256]
    float* out_ln = out0 + (size_t)NN * CC;       // [N, N]

    cudaFuncSetAttribute(k3_main, cudaFuncAttributeMaxDynamicSharedMemorySize, K3_DYN);

    k1_proj_skip_scores<<<128, 256>>>(nodes, pp, sw, ssw, stw);   // 1
    k2_stats<<<dim3(NSTRIP, RC2), 256>>>(deg, bond, cutp);        // 2
    k2bc_combine<<<32, 256>>>();                                  // 3
    k3_main<<<dim3(NJC, NN / IT), 256, K3_DYN>>>();               // 4 (profiled slot)
    kRowLN<<<NN, 256>>>(out_ln);                                  // 5
    k4_epilogue<<<NN * CC / 4 / 256, 256>>>(out0);                // 6
}

// round 14
// speedup vs baseline: 1.1521x; 1.1521x over previous
#include <cuda_runtime.h>

#define NN 4096
#define FIN 128
#define FOUT 64
#define HH 4
#define CC 256            // HH*FOUT
#define NEG_INF (-1e9f)
#define RC2 32            // row chunks in stats pass (128 rows each)
#define NSTRIP 16         // column strips in stats pass
#define NJC 4             // j-chunks in main pass
#define JC 1024           // columns per j-chunk
#define IT 64             // i rows per block in main pass (amortizes B staging)
#define MST 40            // mask smem i-stride: A-frag LDS.64 conflict-free
#define MBUFW (IT * MST)  // 2560 words
#define PJB 72            // B smem jp-stride: B-frag lanes hit 32 distinct banks
#define PHB (16 * PJB)    // per-head: 16 j-pairs = 1152 words
#define PBW (HH * PHB)    // 4608 words
#define K3BUF (MBUFW + PBW)       // 7168 words per stage
#define K3_DYN (2 * K3BUF * 4)    // 57344 bytes dynamic smem

// ---------------- scratch (static device globals; fully rewritten each call) ----------
__device__ float g_proj[HH * NN * FOUT];        // [h][n][f] f32
__device__ unsigned g_projh[HH * (NN / 2) * FOUT]; // proj*cinv, half2 (j-even lo, j-odd hi)
__device__ float g_ssrc[HH * NN];
__device__ float g_stgt[HH * NN];
__device__ float g_skip[NN * CC];
__device__ float g_csp[RC2 * HH * NN];          // col exp-sum partials (shifted by -8)
__device__ float g_mu[NN];                      // shifted mu' (shift cancels in m - mu)
__device__ float g_rstd[NN];
__device__ float g_mask[(size_t)NN * NN];       // 64MB: mask - 8
__device__ float g_agg[NJC * NN * CC];          // partial out per j-chunk

// ---------------- helpers ----------------
__device__ __forceinline__ unsigned long long pk2(float x, float y) {
    unsigned long long r;
    asm("mov.b64 %0, {%1,%2};" : "=l"(r) : "f"(x), "f"(y));
    return r;
}
__device__ __forceinline__ void upk2(unsigned long long v, float& x, float& y) {
    asm("mov.b64 {%0,%1}, %2;" : "=f"(x), "=f"(y) : "l"(v));
}
__device__ __forceinline__ unsigned long long fma2(unsigned long long a,
                                                   unsigned long long b,
                                                   unsigned long long c) {
    unsigned long long d;
    asm("fma.rn.f32x2 %0, %1, %2, %3;" : "=l"(d) : "l"(a), "l"(b), "l"(c));
    return d;
}
// Pack two f32 -> f16x2 (same helper for A and B so hw convention cancels in k-dot)
__device__ __forceinline__ unsigned pkh2(float lo, float hi) {
    unsigned r;
    asm("cvt.rn.f16x2.f32 %0, %2, %1;" : "=r"(r) : "f"(lo), "f"(hi));
    return r;
}
__device__ __forceinline__ void mma_f16(float* d, const unsigned* a,
                                        unsigned b0, unsigned b1) {
    asm volatile(
        "mma.sync.aligned.m16n8k16.row.col.f32.f16.f16.f32 "
        "{%0,%1,%2,%3},{%4,%5,%6,%7},{%8,%9},{%0,%1,%2,%3};"
        : "+f"(d[0]), "+f"(d[1]), "+f"(d[2]), "+f"(d[3])
        : "r"(a[0]), "r"(a[1]), "r"(a[2]), "r"(a[3]), "r"(b0), "r"(b1));
}
__device__ __forceinline__ void cpa16(unsigned dst, const void* src) {
    asm volatile("cp.async.cg.shared.global [%0], [%1], 16;" :: "r"(dst), "l"(src));
}
__device__ __forceinline__ void cpa_commit() {
    asm volatile("cp.async.commit_group;");
}
template <int N> __device__ __forceinline__ void cpa_wait() {
    asm volatile("cp.async.wait_group %0;" :: "n"(N));
}

// ---------------- K1: proj + skip GEMMs (f32x2 packed) + scalar scores --------------
__global__ void k1_proj_skip_scores(const float* __restrict__ nodes,
                                    const float* __restrict__ pp,
                                    const float* __restrict__ sw,
                                    const float* __restrict__ s_src,
                                    const float* __restrict__ s_tgt) {
    __shared__ float nsT[FIN][34];   // transposed, padded: row pairs 8B-aligned
    int tid = threadIdx.x;
    int ib = blockIdx.x * 32;
    for (int x = tid; x < 32 * FIN; x += 256) {
        int row = x >> 7, col = x & 127;
        nsT[col][row] = nodes[ib * FIN + x];
    }
    __syncthreads();
    int c = tid, h = c >> 6, f = c & 63;
    unsigned long long aP2[16], aS2[16];
#pragma unroll
    for (int r = 0; r < 16; r++) { aP2[r] = 0ull; aS2[r] = 0ull; }
#pragma unroll 2
    for (int k = 0; k < FIN; k++) {
        float w1 = pp[h * (FIN * FOUT) + k * FOUT + f];
        float w2 = sw[c * FIN + k];
        unsigned long long W1 = pk2(w1, w1), W2 = pk2(w2, w2);
        const unsigned long long* nv = (const unsigned long long*)&nsT[k][0];
#pragma unroll
        for (int rp = 0; rp < 16; rp++) {
            unsigned long long nn = nv[rp];
            aP2[rp] = fma2(nn, W1, aP2[rp]);
            aS2[rp] = fma2(nn, W2, aS2[rp]);
        }
    }
#pragma unroll
    for (int rp = 0; rp < 16; rp++) {
        float lo, hi;
        upk2(aP2[rp], lo, hi);
        g_proj[(h * NN + ib + 2 * rp) * FOUT + f] = lo;
        g_proj[(h * NN + ib + 2 * rp + 1) * FOUT + f] = hi;
        upk2(aS2[rp], lo, hi);
        g_skip[(ib + 2 * rp) * CC + c] = lo;
        g_skip[(ib + 2 * rp + 1) * CC + c] = hi;
    }
    __syncthreads();   // block-scope visibility of g_proj stores
    {
        int r = tid >> 3;
        int h2 = (tid >> 1) & 3;
        int which = tid & 1;
        const float* pr = &g_proj[(h2 * NN + ib + r) * FOUT];
        const float* wv = (which ? s_tgt : s_src) + h2 * FOUT;
        float a = 0.f;
#pragma unroll 8
        for (int ff = 0; ff < FOUT; ff++) a = fmaf(pr[ff], wv[ff], a);
        if (which) g_stgt[h2 * NN + ib + r] = a;
        else       g_ssrc[h2 * NN + ib + r] = a;
    }
}

// ---------------- K2: stats pass (writes mask-8; col exp-sums ONLY) ----------------
__global__ void k2_stats(const float* __restrict__ deg,
                         const float* __restrict__ bond,
                         const float* __restrict__ cutp) {
    __shared__ float ssS[HH][128];
    int tid = threadIdx.x;
    int s = blockIdx.x, rc = blockIdx.y;
    int j = s * 256 + tid;
    int i0 = rc * 128;
    float cut = *cutp;
    for (int x = tid; x < HH * 128; x += 256)
        ssS[x >> 7][x & 127] = g_ssrc[(x >> 7) * NN + i0 + (x & 127)];
    __syncthreads();
    float st[HH], sm[HH];
#pragma unroll
    for (int h = 0; h < HH; h++) {
        st[h] = g_stgt[h * NN + j];
        sm[h] = 0.f;
    }
    for (int li0 = 0; li0 < 128; li0 += 4) {
        float dv[4], bv[4];
#pragma unroll
        for (int k = 0; k < 4; k++) {
            size_t off = (size_t)(i0 + li0 + k) * NN + j;
            dv[k] = deg[off];
            bv[k] = bond[off];
        }
#pragma unroll
        for (int k = 0; k < 4; k++) {
            int li = li0 + k;
            int i = i0 + li;
            float wdm = dv[k] + bv[k];
            float mask = (wdm > 0.f) ? wdm : ((bv[k] > cut) ? (bv[k] + wdm) : NEG_INF);
            mask -= 8.0f;   // global shift: fp16 exp headroom (cancels in softmax)
            g_mask[(size_t)i * NN + j] = mask;
#pragma unroll
            for (int h = 0; h < HH; h++) {
                float t = ssS[h][li] + st[h];
                float x = fmaxf(t, 0.2f * t) + mask;
                sm[h] += __expf(x);
            }
        }
    }
#pragma unroll
    for (int h = 0; h < HH; h++)
        g_csp[(rc * HH + h) * NN + j] = sm[h];
}

// ---------------- K2bc: projh combine (bx<32) OR per-row mask stats (bx>=32) --------
__global__ void k2bc_combine() {
    __shared__ float sp[8], sq[8];
    int bx = blockIdx.x;
    int tid = threadIdx.x;
    if (bx < 32) {
        int t = bx * 256 + tid;           // 0..8191 = h*2048 + jp
        int h = t >> 11, jp = t & 2047;
        int j0 = 2 * jp, j1 = j0 + 1;
        float S0 = 0.f, S1 = 0.f;
#pragma unroll
        for (int rc = 0; rc < RC2; rc++) {
            S0 += g_csp[(rc * HH + h) * NN + j0];
            S1 += g_csp[(rc * HH + h) * NN + j1];
        }
        float ci0 = 1.0f / S0, ci1 = 1.0f / S1;
        const float4* p0 = (const float4*)&g_proj[((size_t)h * NN + j0) * FOUT];
        const float4* p1 = (const float4*)&g_proj[((size_t)h * NN + j1) * FOUT];
        uint4* dst = (uint4*)&g_projh[((size_t)h * 2048 + jp) * FOUT];
#pragma unroll
        for (int q = 0; q < FOUT / 4; q++) {
            float4 a = p0[q], b = p1[q];
            uint4 o;
            o.x = pkh2(a.x * ci0, b.x * ci1);
            o.y = pkh2(a.y * ci0, b.y * ci1);
            o.z = pkh2(a.z * ci0, b.z * ci1);
            o.w = pkh2(a.w * ci0, b.w * ci1);
            dst[q] = o;
        }
    } else {
        // one block per row: full-row sum/sumsq of mask -> mu, rstd
        int i = bx - 32;
        int lane = tid & 31, w = tid >> 5;
        const float4* src = (const float4*)&g_mask[(size_t)i * NN];
        float s = 0.f, q = 0.f;
#pragma unroll
        for (int t = 0; t < 4; t++) {     // tid + 256t covers all 1024 float4
            float4 v = src[tid + 256 * t];
            s += v.x + v.y + v.z + v.w;
            q = fmaf(v.x, v.x, q);
            q = fmaf(v.y, v.y, q);
            q = fmaf(v.z, v.z, q);
            q = fmaf(v.w, v.w, q);
        }
#pragma unroll
        for (int off = 16; off > 0; off >>= 1) {
            s += __shfl_xor_sync(0xffffffffu, s, off);
            q += __shfl_xor_sync(0xffffffffu, q, off);
        }
        if (lane == 0) { sp[w] = s; sq[w] = q; }
        __syncthreads();
        if (tid == 0) {
            float S = 0.f, Q = 0.f;
#pragma unroll
            for (int x = 0; x < 8; x++) { S += sp[x]; Q += sq[x]; }
            float mu = S * (1.0f / NN);
            float var = Q * (1.0f / NN) - mu * mu;   // shift-invariant
            g_mu[i] = mu;
            g_rstd[i] = rsqrtf(var + 1e-5f);
        }
    }
}

// ---------------- K3: fp16 m16n8k16 attn@projc + fused LN write, cp.async 2-buf -----
// grid (NJC, 64), block 256 = 8 warps. Warp w: head h=w&3, i-half=w>>2.
__global__ __launch_bounds__(256) void k3_main(float* __restrict__ out_ln) {
    extern __shared__ float smdyn[];
    unsigned sbase = (unsigned)__cvta_generic_to_shared(smdyn);
    int tid = threadIdx.x;
    int jc = blockIdx.x;
    int ib = blockIdx.y * IT;

    int lane = tid & 31;
    int w = tid >> 5;
    int h = w & 3;
    int ihalf = w >> 2;
    int t4 = lane & 3, tg4 = lane >> 2;

    int rbase = ihalf * 32 + tg4;
    float ssv[4];
#pragma unroll
    for (int u = 0; u < 4; u++)
        ssv[u] = g_ssrc[h * NN + ib + rbase + 8 * u];

    // LN mapping: thread owns rows mi, mi+32 and 4-wide j chunk
    int mi = tid >> 3, mjq = (tid & 7) * 4;
    float mu0 = g_mu[ib + mi], rs0 = g_rstd[ib + mi];
    float mu1 = g_mu[ib + mi + 32], rs1 = g_rstd[ib + mi + 32];

    float acc[2][8][4];
#pragma unroll
    for (int mt = 0; mt < 2; mt++)
#pragma unroll
        for (int nt = 0; nt < 8; nt++)
#pragma unroll
            for (int e = 0; e < 4; e++) acc[mt][nt][e] = 0.f;

    auto stage = [&](int t, int buf) {
        int jb = jc * JC + t * 32;
        unsigned mb = sbase + (buf * K3BUF) * 4;
        unsigned pb = mb + MBUFW * 4;
        // mask tile: 64 i x 32 j
        cpa16(mb + (mi * MST + mjq) * 4,
              &g_mask[(size_t)(ib + mi) * NN + jb + mjq]);
        cpa16(mb + ((mi + 32) * MST + mjq) * 4,
              &g_mask[(size_t)(ib + mi + 32) * NN + jb + mjq]);
        // projh tile: [h][jp 0..15][f 0..63] half2 words
#pragma unroll
        for (int x = 0; x < 4; x++) {
            int c = tid + x * 256;               // 0..1023
            int hh = c >> 8, jp = (c >> 4) & 15, f4 = (c & 15) * 4;
            cpa16(pb + (hh * PHB + jp * PJB + f4) * 4,
                  &g_projh[((size_t)hh * 2048 + (jb >> 1) + jp) * FOUT + f4]);
        }
        cpa_commit();
    };

    stage(0, 0);

    for (int t0 = 0; t0 < JC / 32; t0++) {
        if (t0 + 1 < JC / 32) {
            stage(t0 + 1, (t0 + 1) & 1);
            cpa_wait<1>();
        } else {
            cpa_wait<0>();
        }
        __syncthreads();

        int jb = jc * JC + t0 * 32;
        const float* mb = smdyn + (t0 & 1) * K3BUF;
        const unsigned* pS = (const unsigned*)(mb + MBUFW);

        // ---- fused LN write from staged mask ----
        {
            float4 v0 = *(const float4*)&mb[mi * MST + mjq];
            float4 v1 = *(const float4*)&mb[(mi + 32) * MST + mjq];
            float4 r0, r1;
            r0.x = (v0.x - mu0) * rs0; r0.y = (v0.y - mu0) * rs0;
            r0.z = (v0.z - mu0) * rs0; r0.w = (v0.w - mu0) * rs0;
            r1.x = (v1.x - mu1) * rs1; r1.y = (v1.y - mu1) * rs1;
            r1.z = (v1.z - mu1) * rs1; r1.w = (v1.w - mu1) * rs1;
            *(float4*)&out_ln[(size_t)(ib + mi) * NN + jb + mjq] = r0;
            *(float4*)&out_ln[(size_t)(ib + mi + 32) * NN + jb + mjq] = r1;
        }

#pragma unroll
        for (int kt = 0; kt < 2; kt++) {
            int cb = kt * 16 + 2 * t4;                 // j col base in tile
            float2 stA = *(const float2*)&g_stgt[h * NN + jb + cb];      // j0, j0+1
            float2 stB = *(const float2*)&g_stgt[h * NN + jb + cb + 8];  // j0+8, j0+9
            unsigned a[2][4];
#pragma unroll
            for (int mt = 0; mt < 2; mt++) {
                int r_ = ihalf * 32 + mt * 16 + tg4;
                float2 mA0 = *(const float2*)&mb[r_ * MST + cb];
                float2 mA1 = *(const float2*)&mb[(r_ + 8) * MST + cb];
                float2 mB0 = *(const float2*)&mb[r_ * MST + cb + 8];
                float2 mB1 = *(const float2*)&mb[(r_ + 8) * MST + cb + 8];
                float s0 = ssv[2 * mt], s1 = ssv[2 * mt + 1];
                float t00 = s0 + stA.x, t01 = s0 + stA.y;
                float t10 = s1 + stA.x, t11 = s1 + stA.y;
                float t02 = s0 + stB.x, t03 = s0 + stB.y;
                float t12 = s1 + stB.x, t13 = s1 + stB.y;
                float e00 = __expf(fmaxf(t00, 0.2f * t00) + mA0.x);
                float e01 = __expf(fmaxf(t01, 0.2f * t01) + mA0.y);
                float e10 = __expf(fmaxf(t10, 0.2f * t10) + mA1.x);
                float e11 = __expf(fmaxf(t11, 0.2f * t11) + mA1.y);
                float e02 = __expf(fmaxf(t02, 0.2f * t02) + mB0.x);
                float e03 = __expf(fmaxf(t03, 0.2f * t03) + mB0.y);
                float e12 = __expf(fmaxf(t12, 0.2f * t12) + mB1.x);
                float e13 = __expf(fmaxf(t13, 0.2f * t13) + mB1.y);
                a[mt][0] = pkh2(e00, e01);   // row r_,   k-low pair
                a[mt][1] = pkh2(e10, e11);   // row r_+8, k-low pair
                a[mt][2] = pkh2(e02, e03);   // row r_,   k-high pair
                a[mt][3] = pkh2(e12, e13);   // row r_+8, k-high pair
            }
            const unsigned* pbp = &pS[h * PHB + (kt * 8 + t4) * PJB + tg4];
#pragma unroll
            for (int nt = 0; nt < 8; nt++) {
                unsigned b0 = pbp[nt * 8];
                unsigned b1 = pbp[nt * 8 + 4 * PJB];
                mma_f16(acc[0][nt], a[0], b0, b1);
                mma_f16(acc[1][nt], a[1], b0, b1);
            }
        }
        __syncthreads();
    }
    // ---- epilogue: fragment store to g_agg ----
#pragma unroll
    for (int mt = 0; mt < 2; mt++)
#pragma unroll
        for (int nt = 0; nt < 8; nt++) {
            int i0 = ib + ihalf * 32 + mt * 16 + tg4;
            int c0 = h * 64 + nt * 8 + 2 * t4;
            *(float2*)&g_agg[((size_t)jc * NN + i0) * CC + c0] =
                make_float2(acc[mt][nt][0], acc[mt][nt][1]);
            *(float2*)&g_agg[((size_t)jc * NN + i0 + 8) * CC + c0] =
                make_float2(acc[mt][nt][2], acc[mt][nt][3]);
        }
}

// ---------------- K4: epilogue: sum partials + skip, ELU (float4) ----------------
__global__ void k4_epilogue(float* __restrict__ out0) {
    int t = blockIdx.x * 256 + threadIdx.x;
    const float4* sk = (const float4*)g_skip;
    float4 v = sk[t];
#pragma unroll
    for (int jc = 0; jc < NJC; jc++) {
        float4 a = ((const float4*)g_agg)[(size_t)jc * (NN * CC / 4) + t];
        v.x += a.x; v.y += a.y; v.z += a.z; v.w += a.w;
    }
    float4 r;
    r.x = (v.x > 0.f) ? v.x : expm1f(v.x);
    r.y = (v.y > 0.f) ? v.y : expm1f(v.y);
    r.z = (v.z > 0.f) ? v.z : expm1f(v.z);
    r.w = (v.w > 0.f) ? v.w : expm1f(v.w);
    ((float4*)out0)[t] = r;
}

// ---------------- launch ----------------
extern "C" void kernel_launch(void* const* d_in, const int* in_sizes, int n_in,
                              void* d_out, int out_size) {
    const float* nodes = (const float*)d_in[0];
    const float* deg   = (const float*)d_in[1];
    const float* bond  = (const float*)d_in[3];
    const float* pp    = (const float*)d_in[4];
    const float* ssw   = (const float*)d_in[5];
    const float* stw   = (const float*)d_in[6];
    const float* sw    = (const float*)d_in[7];
    const float* cutp  = (const float*)d_in[8];

    float* out0 = (float*)d_out;                  // [N, 256]
    float* out_ln = out0 + (size_t)NN * CC;       // [N, N]

    cudaFuncSetAttribute(k3_main, cudaFuncAttributeMaxDynamicSharedMemorySize, K3_DYN);

    k1_proj_skip_scores<<<128, 256>>>(nodes, pp, sw, ssw, stw);   // 1
    k2_stats<<<dim3(NSTRIP, RC2), 256>>>(deg, bond, cutp);        // 2
    k2bc_combine<<<32 + NN, 256>>>();                             // 3 (projh + row stats)
    k3_main<<<dim3(NJC, NN / IT), 256, K3_DYN>>>(out_ln);         // 4 (profiled slot)
    k4_epilogue<<<NN * CC / 4 / 256, 256>>>(out0);                // 5
}

// round 15
// speedup vs baseline: 1.2119x; 1.0520x over previous
#include <cuda_runtime.h>

#define NN 4096
#define FIN 128
#define FOUT 64
#define HH 4
#define CC 256            // HH*FOUT
#define NEG_INF (-1e9f)
#define LOG2E 1.44269504f
#define RC2 32            // row chunks in stats pass (128 rows each)
#define NSTRIP 16         // column strips in stats pass
#define NJC 4             // j-chunks in main pass
#define JC 1024           // columns per j-chunk
#define IT 64             // i rows per block in main pass
#define MST 40            // mask smem i-stride: A-frag LDS.64 conflict-free
#define MBUFW (IT * MST)  // 2560 words
#define PGS 136           // B smem pairgroup stride (words): LDS.64 conflict-free
#define PHB2 (8 * PGS)    // per-head per-tile: 8 pairgroups = 1088 words
#define PBW2 (HH * PHB2)  // 4352 words
#define SSOFF (MBUFW + PBW2)      // 6912: stgt tile (128 words)
#define K3BUF (SSOFF + 128)       // 7040 words per stage
#define K3_DYN (2 * K3BUF * 4)    // 56320 bytes dynamic smem

// ---------------- scratch (static device globals; fully rewritten each call) ----------
__device__ float g_proj[HH * NN * FOUT];        // [h][n][f] f32
__device__ unsigned g_projh2[HH * 128 * 8 * 128]; // proj*cinv f16, MMA-tile order
__device__ float g_ssrc[HH * NN];               // pre-scaled by log2(e)
__device__ float g_stgt[HH * NN];               // pre-scaled by log2(e)
__device__ float g_skip[NN * CC];
__device__ float g_csp[RC2 * HH * NN];          // col exp-sum partials
__device__ float g_mu[NN];
__device__ float g_rstd[NN];
__device__ float g_mask[(size_t)NN * NN];       // 64MB: (mask - 8) * log2(e)
__device__ float g_agg[NJC * NN * CC];          // partial out per j-chunk

// ---------------- helpers ----------------
__device__ __forceinline__ unsigned long long pk2(float x, float y) {
    unsigned long long r;
    asm("mov.b64 %0, {%1,%2};" : "=l"(r) : "f"(x), "f"(y));
    return r;
}
__device__ __forceinline__ void upk2(unsigned long long v, float& x, float& y) {
    asm("mov.b64 {%0,%1}, %2;" : "=f"(x), "=f"(y) : "l"(v));
}
__device__ __forceinline__ unsigned long long fma2(unsigned long long a,
                                                   unsigned long long b,
                                                   unsigned long long c) {
    unsigned long long d;
    asm("fma.rn.f32x2 %0, %1, %2, %3;" : "=l"(d) : "l"(a), "l"(b), "l"(c));
    return d;
}
__device__ __forceinline__ float ex2f(float x) {    // exp with pre-scaled arg
    float r;
    asm("ex2.approx.f32 %0, %1;" : "=f"(r) : "f"(x));
    return r;
}
// Pack two f32 -> f16x2 (same helper for A and B so hw convention cancels in k-dot)
__device__ __forceinline__ unsigned pkh2(float lo, float hi) {
    unsigned r;
    asm("cvt.rn.f16x2.f32 %0, %2, %1;" : "=r"(r) : "f"(lo), "f"(hi));
    return r;
}
__device__ __forceinline__ void mma_f16(float* d, const unsigned* a,
                                        unsigned b0, unsigned b1) {
    asm volatile(
        "mma.sync.aligned.m16n8k16.row.col.f32.f16.f16.f32 "
        "{%0,%1,%2,%3},{%4,%5,%6,%7},{%8,%9},{%0,%1,%2,%3};"
        : "+f"(d[0]), "+f"(d[1]), "+f"(d[2]), "+f"(d[3])
        : "r"(a[0]), "r"(a[1]), "r"(a[2]), "r"(a[3]), "r"(b0), "r"(b1));
}
__device__ __forceinline__ void cpa16(unsigned dst, const void* src) {
    asm volatile("cp.async.cg.shared.global [%0], [%1], 16;" :: "r"(dst), "l"(src));
}
__device__ __forceinline__ void cpa_commit() {
    asm volatile("cp.async.commit_group;");
}
template <int N> __device__ __forceinline__ void cpa_wait() {
    asm volatile("cp.async.wait_group %0;" :: "n"(N));
}

// ---------------- K1: proj + skip GEMMs (f32x2 packed) + scaled scores --------------
__global__ void k1_proj_skip_scores(const float* __restrict__ nodes,
                                    const float* __restrict__ pp,
                                    const float* __restrict__ sw,
                                    const float* __restrict__ s_src,
                                    const float* __restrict__ s_tgt) {
    __shared__ float nsT[FIN][34];   // transposed, padded: row pairs 8B-aligned
    int tid = threadIdx.x;
    int ib = blockIdx.x * 32;
    for (int x = tid; x < 32 * FIN; x += 256) {
        int row = x >> 7, col = x & 127;
        nsT[col][row] = nodes[ib * FIN + x];
    }
    __syncthreads();
    int c = tid, h = c >> 6, f = c & 63;
    unsigned long long aP2[16], aS2[16];
#pragma unroll
    for (int r = 0; r < 16; r++) { aP2[r] = 0ull; aS2[r] = 0ull; }
#pragma unroll 2
    for (int k = 0; k < FIN; k++) {
        float w1 = pp[h * (FIN * FOUT) + k * FOUT + f];
        float w2 = sw[c * FIN + k];
        unsigned long long W1 = pk2(w1, w1), W2 = pk2(w2, w2);
        const unsigned long long* nv = (const unsigned long long*)&nsT[k][0];
#pragma unroll
        for (int rp = 0; rp < 16; rp++) {
            unsigned long long nn = nv[rp];
            aP2[rp] = fma2(nn, W1, aP2[rp]);
            aS2[rp] = fma2(nn, W2, aS2[rp]);
        }
    }
#pragma unroll
    for (int rp = 0; rp < 16; rp++) {
        float lo, hi;
        upk2(aP2[rp], lo, hi);
        g_proj[(h * NN + ib + 2 * rp) * FOUT + f] = lo;
        g_proj[(h * NN + ib + 2 * rp + 1) * FOUT + f] = hi;
        upk2(aS2[rp], lo, hi);
        g_skip[(ib + 2 * rp) * CC + c] = lo;
        g_skip[(ib + 2 * rp + 1) * CC + c] = hi;
    }
    __syncthreads();   // block-scope visibility of g_proj stores
    {
        int r = tid >> 3;
        int h2 = (tid >> 1) & 3;
        int which = tid & 1;
        const float* pr = &g_proj[(h2 * NN + ib + r) * FOUT];
        const float* wv = (which ? s_tgt : s_src) + h2 * FOUT;
        float a = 0.f;
#pragma unroll 8
        for (int ff = 0; ff < FOUT; ff++) a = fmaf(pr[ff], wv[ff], a);
        a *= LOG2E;   // pre-scale for ex2
        if (which) g_stgt[h2 * NN + ib + r] = a;
        else       g_ssrc[h2 * NN + ib + r] = a;
    }
}

// ---------------- K2: stats pass (writes scaled mask; col exp-sums) ----------------
__global__ void k2_stats(const float* __restrict__ deg,
                         const float* __restrict__ bond,
                         const float* __restrict__ cutp) {
    __shared__ float ssS[HH][128];
    int tid = threadIdx.x;
    int s = blockIdx.x, rc = blockIdx.y;
    int j = s * 256 + tid;
    int i0 = rc * 128;
    float cut = *cutp;
    for (int x = tid; x < HH * 128; x += 256)
        ssS[x >> 7][x & 127] = g_ssrc[(x >> 7) * NN + i0 + (x & 127)];
    __syncthreads();
    float st[HH], sm[HH];
#pragma unroll
    for (int h = 0; h < HH; h++) {
        st[h] = g_stgt[h * NN + j];
        sm[h] = 0.f;
    }
    for (int li0 = 0; li0 < 128; li0 += 4) {
        float dv[4], bv[4];
#pragma unroll
        for (int k = 0; k < 4; k++) {
            size_t off = (size_t)(i0 + li0 + k) * NN + j;
            dv[k] = deg[off];
            bv[k] = bond[off];
        }
#pragma unroll
        for (int k = 0; k < 4; k++) {
            int li = li0 + k;
            int i = i0 + li;
            float wdm = dv[k] + bv[k];
            float mask = (wdm > 0.f) ? wdm : ((bv[k] > cut) ? (bv[k] + wdm) : NEG_INF);
            // (mask - 8) * log2e: -8 shift = fp16 headroom (cancels in softmax);
            // log2e scale lets ex2 replace exp. LN is affine-invariant to both.
            float m2 = fmaf(mask, LOG2E, -8.0f * LOG2E);
            g_mask[(size_t)i * NN + j] = m2;
#pragma unroll
            for (int h = 0; h < HH; h++) {
                float t = ssS[h][li] + st[h];
                sm[h] += ex2f(fmaxf(t, 0.2f * t) + m2);
            }
        }
    }
#pragma unroll
    for (int h = 0; h < HH; h++)
        g_csp[(rc * HH + h) * NN + j] = sm[h];
}

// ---------------- K2bc: build g_projh2 (MMA-tile order) OR per-row mask stats -------
__global__ void k2bc_combine() {
    __shared__ float sp[8], sq[8];
    int bx = blockIdx.x;
    int tid = threadIdx.x;
    if (bx < 64) {
        // part A: one warp per (h, tile). lane: pg = lane>>2, q = lane&3.
        int w = tid >> 5, lane = tid & 31;
        int wid = bx * 8 + w;             // 0..511
        int h = wid >> 7, tile = wid & 127;
        int pg = lane >> 2, q = lane & 3;
        int kt = pg >> 2, t4 = pg & 3;
        int jpl0 = kt * 8 + t4, jpl1 = jpl0 + 4;
        int jp0 = tile * 16 + jpl0, jp1 = tile * 16 + jpl1;
        int c0 = 2 * jp0, c1 = c0 + 1, c2 = 2 * jp1, c3 = c2 + 1;
        int cq = (q == 0) ? c0 : (q == 1) ? c1 : (q == 2) ? c2 : c3;
        float S = 0.f;
#pragma unroll 4
        for (int rc = 0; rc < RC2; rc++)
            S += g_csp[(rc * HH + h) * NN + cq];
        float ci = 1.0f / S;
        int qb = lane & ~3;
        float ci0 = __shfl_sync(0xffffffffu, ci, qb + 0);
        float ci1 = __shfl_sync(0xffffffffu, ci, qb + 1);
        float ci2 = __shfl_sync(0xffffffffu, ci, qb + 2);
        float ci3 = __shfl_sync(0xffffffffu, ci, qb + 3);
        int fq = q * 16;
        const float* r0 = &g_proj[((size_t)h * NN + c0) * FOUT];
        const float* r1 = &g_proj[((size_t)h * NN + c1) * FOUT];
        const float* r2 = &g_proj[((size_t)h * NN + c2) * FOUT];
        const float* r3 = &g_proj[((size_t)h * NN + c3) * FOUT];
        unsigned base = (((h * 128 + tile) * 8 + pg) << 7) + fq * 2;  // word index
#pragma unroll
        for (int x = 0; x < 4; x++) {
            int f = fq + x * 4;
            float4 a0 = *(const float4*)&r0[f];
            float4 a1 = *(const float4*)&r1[f];
            float4 a2 = *(const float4*)&r2[f];
            float4 a3 = *(const float4*)&r3[f];
            uint4 u0, u1;
            u0.x = pkh2(a0.x * ci0, a1.x * ci1);
            u0.y = pkh2(a2.x * ci2, a3.x * ci3);
            u0.z = pkh2(a0.y * ci0, a1.y * ci1);
            u0.w = pkh2(a2.y * ci2, a3.y * ci3);
            u1.x = pkh2(a0.z * ci0, a1.z * ci1);
            u1.y = pkh2(a2.z * ci2, a3.z * ci3);
            u1.z = pkh2(a0.w * ci0, a1.w * ci1);
            u1.w = pkh2(a2.w * ci2, a3.w * ci3);
            *(uint4*)&g_projh2[base + x * 8] = u0;
            *(uint4*)&g_projh2[base + x * 8 + 4] = u1;
        }
    } else {
        // part B: one block per row: full-row sum/sumsq of (scaled) mask -> mu, rstd
        int i = bx - 64;
        int lane = tid & 31, w = tid >> 5;
        const float4* src = (const float4*)&g_mask[(size_t)i * NN];
        float s = 0.f, q = 0.f;
#pragma unroll
        for (int t = 0; t < 4; t++) {
            float4 v = src[tid + 256 * t];
            s += v.x + v.y + v.z + v.w;
            q = fmaf(v.x, v.x, q);
            q = fmaf(v.y, v.y, q);
            q = fmaf(v.z, v.z, q);
            q = fmaf(v.w, v.w, q);
        }
#pragma unroll
        for (int off = 16; off > 0; off >>= 1) {
            s += __shfl_xor_sync(0xffffffffu, s, off);
            q += __shfl_xor_sync(0xffffffffu, q, off);
        }
        if (lane == 0) { sp[w] = s; sq[w] = q; }
        __syncthreads();
        if (tid == 0) {
            float S = 0.f, Q = 0.f;
#pragma unroll
            for (int x = 0; x < 8; x++) { S += sp[x]; Q += sq[x]; }
            float mu = S * (1.0f / NN);
            float var = Q * (1.0f / NN) - mu * mu;   // scaled-domain stats: LN invariant
            g_mu[i] = mu;
            g_rstd[i] = rsqrtf(var + 1e-5f);
        }
    }
}

// ---------------- K3: fp16 m16n8k16 attn@projc + fused LN write, cp.async 2-buf -----
// grid (NJC, 64), block 256 = 8 warps. Warp w: head h=w&3, i-half=w>>2.
__global__ __launch_bounds__(256) void k3_main(float* __restrict__ out_ln) {
    extern __shared__ float smdyn[];
    unsigned sbase = (unsigned)__cvta_generic_to_shared(smdyn);
    int tid = threadIdx.x;
    int jc = blockIdx.x;
    int ib = blockIdx.y * IT;

    int lane = tid & 31;
    int w = tid >> 5;
    int h = w & 3;
    int ihalf = w >> 2;
    int t4 = lane & 3, tg4 = lane >> 2;

    int rbase = ihalf * 32 + tg4;
    float ssv[4];
#pragma unroll
    for (int u = 0; u < 4; u++)
        ssv[u] = g_ssrc[h * NN + ib + rbase + 8 * u];

    // LN mapping: thread owns rows mi, mi+32 and 4-wide j chunk
    int mi = tid >> 3, mjq = (tid & 7) * 4;
    float mu0 = g_mu[ib + mi], rs0 = g_rstd[ib + mi];
    float mu1 = g_mu[ib + mi + 32], rs1 = g_rstd[ib + mi + 32];

    float acc[2][8][4];
#pragma unroll
    for (int mt = 0; mt < 2; mt++)
#pragma unroll
        for (int nt = 0; nt < 8; nt++)
#pragma unroll
            for (int e = 0; e < 4; e++) acc[mt][nt][e] = 0.f;

    auto stage = [&](int t, int buf) {
        int jb = jc * JC + t * 32;
        int tile = jb >> 5;
        unsigned mb = sbase + (buf * K3BUF) * 4;
        unsigned pb = mb + MBUFW * 4;
        // mask tile: 64 i x 32 j
        cpa16(mb + (mi * MST + mjq) * 4,
              &g_mask[(size_t)(ib + mi) * NN + jb + mjq]);
        cpa16(mb + ((mi + 32) * MST + mjq) * 4,
              &g_mask[(size_t)(ib + mi + 32) * NN + jb + mjq]);
        // projh2 tile: contiguous source, padded dst (pg stride 136)
#pragma unroll
        for (int x = 0; x < 4; x++) {
            int c = tid + x * 256;               // 0..1023
            int hh = c >> 8, cc = c & 255;
            int pg = cc >> 5, fw = (cc & 31) * 4;
            cpa16(pb + (hh * PHB2 + pg * PGS + fw) * 4,
                  &g_projh2[(((hh * 128 + tile) * 8 + pg) << 7) + fw]);
        }
        // stgt tile: 4h x 32j
        if (tid < 32) {
            int hh = tid >> 3, j8 = tid & 7;
            cpa16(mb + (SSOFF + hh * 32 + j8 * 4) * 4,
                  &g_stgt[hh * NN + jb + j8 * 4]);
        }
        cpa_commit();
    };

    stage(0, 0);

    for (int t0 = 0; t0 < JC / 32; t0++) {
        if (t0 + 1 < JC / 32) {
            stage(t0 + 1, (t0 + 1) & 1);
            cpa_wait<1>();
        } else {
            cpa_wait<0>();
        }
        __syncthreads();

        int jb = jc * JC + t0 * 32;
        const float* mb = smdyn + (t0 & 1) * K3BUF;
        const unsigned* pS = (const unsigned*)(mb + MBUFW);
        const float* sS = mb + SSOFF;

        // ---- fused LN write from staged (scaled) mask ----
        {
            float4 v0 = *(const float4*)&mb[mi * MST + mjq];
            float4 v1 = *(const float4*)&mb[(mi + 32) * MST + mjq];
            float4 r0, r1;
            r0.x = (v0.x - mu0) * rs0; r0.y = (v0.y - mu0) * rs0;
            r0.z = (v0.z - mu0) * rs0; r0.w = (v0.w - mu0) * rs0;
            r1.x = (v1.x - mu1) * rs1; r1.y = (v1.y - mu1) * rs1;
            r1.z = (v1.z - mu1) * rs1; r1.w = (v1.w - mu1) * rs1;
            *(float4*)&out_ln[(size_t)(ib + mi) * NN + jb + mjq] = r0;
            *(float4*)&out_ln[(size_t)(ib + mi + 32) * NN + jb + mjq] = r1;
        }

#pragma unroll
        for (int kt = 0; kt < 2; kt++) {
            int cb = kt * 16 + 2 * t4;                 // j col base in tile
            float2 stA = *(const float2*)&sS[h * 32 + cb];
            float2 stB = *(const float2*)&sS[h * 32 + cb + 8];
            unsigned a[2][4];
#pragma unroll
            for (int mt = 0; mt < 2; mt++) {
                int r_ = ihalf * 32 + mt * 16 + tg4;
                float2 mA0 = *(const float2*)&mb[r_ * MST + cb];
                float2 mA1 = *(const float2*)&mb[(r_ + 8) * MST + cb];
                float2 mB0 = *(const float2*)&mb[r_ * MST + cb + 8];
                float2 mB1 = *(const float2*)&mb[(r_ + 8) * MST + cb + 8];
                float s0 = ssv[2 * mt], s1 = ssv[2 * mt + 1];
                float t00 = s0 + stA.x, t01 = s0 + stA.y;
                float t10 = s1 + stA.x, t11 = s1 + stA.y;
                float t02 = s0 + stB.x, t03 = s0 + stB.y;
                float t12 = s1 + stB.x, t13 = s1 + stB.y;
                float e00 = ex2f(fmaxf(t00, 0.2f * t00) + mA0.x);
                float e01 = ex2f(fmaxf(t01, 0.2f * t01) + mA0.y);
                float e10 = ex2f(fmaxf(t10, 0.2f * t10) + mA1.x);
                float e11 = ex2f(fmaxf(t11, 0.2f * t11) + mA1.y);
                float e02 = ex2f(fmaxf(t02, 0.2f * t02) + mB0.x);
                float e03 = ex2f(fmaxf(t03, 0.2f * t03) + mB0.y);
                float e12 = ex2f(fmaxf(t12, 0.2f * t12) + mB1.x);
                float e13 = ex2f(fmaxf(t13, 0.2f * t13) + mB1.y);
                a[mt][0] = pkh2(e00, e01);   // row r_,   k-low pair
                a[mt][1] = pkh2(e10, e11);   // row r_+8, k-low pair
                a[mt][2] = pkh2(e02, e03);   // row r_,   k-high pair
                a[mt][3] = pkh2(e12, e13);   // row r_+8, k-high pair
            }
            const uint2* pbp = (const uint2*)&pS[h * PHB2 + (kt * 4 + t4) * PGS];
#pragma unroll
            for (int nt = 0; nt < 8; nt++) {
                uint2 b01 = pbp[nt * 8 + tg4];
                mma_f16(acc[0][nt], a[0], b01.x, b01.y);
                mma_f16(acc[1][nt], a[1], b01.x, b01.y);
            }
        }
        __syncthreads();
    }
    // ---- epilogue: fragment store to g_agg ----
#pragma unroll
    for (int mt = 0; mt < 2; mt++)
#pragma unroll
        for (int nt = 0; nt < 8; nt++) {
            int i0 = ib + ihalf * 32 + mt * 16 + tg4;
            int c0 = h * 64 + nt * 8 + 2 * t4;
            *(float2*)&g_agg[((size_t)jc * NN + i0) * CC + c0] =
                make_float2(acc[mt][nt][0], acc[mt][nt][1]);
            *(float2*)&g_agg[((size_t)jc * NN + i0 + 8) * CC + c0] =
                make_float2(acc[mt][nt][2], acc[mt][nt][3]);
        }
}

// ---------------- K4: epilogue: sum partials + skip, ELU (float4) ----------------
__global__ void k4_epilogue(float* __restrict__ out0) {
    int t = blockIdx.x * 256 + threadIdx.x;
    const float4* sk = (const float4*)g_skip;
    float4 v = sk[t];
#pragma unroll
    for (int jc = 0; jc < NJC; jc++) {
        float4 a = ((const float4*)g_agg)[(size_t)jc * (NN * CC / 4) + t];
        v.x += a.x; v.y += a.y; v.z += a.z; v.w += a.w;
    }
    float4 r;
    r.x = (v.x > 0.f) ? v.x : expm1f(v.x);
    r.y = (v.y > 0.f) ? v.y : expm1f(v.y);
    r.z = (v.z > 0.f) ? v.z : expm1f(v.z);
    r.w = (v.w > 0.f) ? v.w : expm1f(v.w);
    ((float4*)out0)[t] = r;
}

// ---------------- launch ----------------
extern "C" void kernel_launch(void* const* d_in, const int* in_sizes, int n_in,
                              void* d_out, int out_size) {
    const float* nodes = (const float*)d_in[0];
    const float* deg   = (const float*)d_in[1];
    const float* bond  = (const float*)d_in[3];
    const float* pp    = (const float*)d_in[4];
    const float* ssw   = (const float*)d_in[5];
    const float* stw   = (const float*)d_in[6];
    const float* sw    = (const float*)d_in[7];
    const float* cutp  = (const float*)d_in[8];

    float* out0 = (float*)d_out;                  // [N, 256]
    float* out_ln = out0 + (size_t)NN * CC;       // [N, N]

    cudaFuncSetAttribute(k3_main, cudaFuncAttributeMaxDynamicSharedMemorySize, K3_DYN);

    k1_proj_skip_scores<<<128, 256>>>(nodes, pp, sw, ssw, stw);   // 1
    k2_stats<<<dim3(NSTRIP, RC2), 256>>>(deg, bond, cutp);        // 2
    k2bc_combine<<<64 + NN, 256>>>();                             // 3 (projh2 + row stats)
    k3_main<<<dim3(NJC, NN / IT), 256, K3_DYN>>>(out_ln);         // 4 (profiled slot)
    k4_epilogue<<<NN * CC / 4 / 256, 256>>>(out0);                // 5
}